// round 13
// baseline (speedup 1.0000x reference)
#include <cuda_runtime.h>
#include <math.h>

#define BD   64
#define CD   256
#define ATTR 300
#define HWD  784
#define O1   32
#define TILE 64

__device__ float g_V[BD * CD];           // v[b][j] = s1[j] * emb[b][j]
__device__ float g_N[BD * CD * O1];      // folded [b][c][o] matrix

// ---- f32x2 packed helpers ---------------------------------------------------
__device__ __forceinline__ unsigned long long pack2(float a, float b) {
    unsigned long long r;
    asm("mov.b64 %0, {%1, %2};" : "=l"(r)
        : "r"(__float_as_uint(a)), "r"(__float_as_uint(b)));
    return r;
}
__device__ __forceinline__ unsigned long long fma2(unsigned long long a,
                                                   unsigned long long b,
                                                   unsigned long long c) {
    unsigned long long d;
    asm("fma.rn.f32x2 %0, %1, %2, %3;" : "=l"(d) : "l"(a), "l"(b), "l"(c));
    return d;
}
__device__ __forceinline__ unsigned long long add2(unsigned long long a,
                                                   unsigned long long b) {
    unsigned long long d;
    asm("add.rn.f32x2 %0, %1, %2;" : "=l"(d) : "l"(a), "l"(b));
    return d;
}
__device__ __forceinline__ float2 unpack2(unsigned long long v) {
    float2 f;
    f.x = __uint_as_float((unsigned)v);
    f.y = __uint_as_float((unsigned)(v >> 32));
    return f;
}
// ---- cp.async helpers -------------------------------------------------------
__device__ __forceinline__ void cpa16(unsigned int dst_smem, const void* src) {
    asm volatile("cp.async.cg.shared.global [%0], [%1], 16;"
                 :: "r"(dst_smem), "l"(src));
}
__device__ __forceinline__ void cpa_commit_wait() {
    asm volatile("cp.async.commit_group;");
    asm volatile("cp.async.wait_group 0;" ::: "memory");
}

// ---------------------------------------------------------------------------
// K1 v2: v[b,j] = s1[j] * (attr_one_hot[b] . W_emb[j] + b_emb[j])
// grid (8 jg, 8 batch-groups), 256 threads. Each warp loads its W_emb quad
// slice wv[4][10] ONCE and reuses it for 8 batches (attr rows in smem):
// W_emb traffic 19.6 MB -> 2.5 MB, load latency amortized 8x.
// Accumulation order per (b,j) identical to R12 -> bitwise-same g_V.
// ---------------------------------------------------------------------------
#define BG 8
__global__ void __launch_bounds__(256, 4)
k1_emb(const float* __restrict__ attr_one_hot,
       const float* __restrict__ W_emb,
       const float* __restrict__ b_emb,
       const float* __restrict__ s1) {
    __shared__ float attr_sm[BG][304];          // 8 batches, padded rows

    const int jg   = blockIdx.x;                // 0..7
    const int bg   = blockIdx.y;                // 0..7
    const int tid  = threadIdx.x;
    const int lane = tid & 31;
    const int wrp  = tid >> 5;

    for (int idx = tid; idx < BG * ATTR; idx += 256) {
        int bi = idx / ATTR;
        int a  = idx - bi * ATTR;
        attr_sm[bi][a] = attr_one_hot[(bg * BG + bi) * ATTR + a];
    }
    __syncthreads();

    const int j0 = jg * 32 + wrp * 4;
    float wv[4][10];
#pragma unroll
    for (int k = 0; k < 10; k++) {
        const int  a  = lane + 32 * k;
        const bool ok = (a < ATTR);
#pragma unroll
        for (int q = 0; q < 4; q++)
            wv[q][k] = ok ? W_emb[(size_t)(j0 + q) * ATTR + a] : 0.f;
    }

    float be[4], sj[4];
#pragma unroll
    for (int q = 0; q < 4; q++) { be[q] = b_emb[j0 + q]; sj[q] = s1[j0 + q]; }

#pragma unroll
    for (int bi = 0; bi < BG; bi++) {
        const int b = bg * BG + bi;
        float p0 = 0.f, p1 = 0.f, p2 = 0.f, p3 = 0.f;
#pragma unroll
        for (int k = 0; k < 10; k++) {
            const int   a  = lane + 32 * k;
            const float av = (a < ATTR) ? attr_sm[bi][a] : 0.f;
            p0 += av * wv[0][k];
            p1 += av * wv[1][k];
            p2 += av * wv[2][k];
            p3 += av * wv[3][k];
        }
#pragma unroll
        for (int off = 16; off >= 1; off >>= 1) {
            p0 += __shfl_xor_sync(0xFFFFFFFFu, p0, off);
            p1 += __shfl_xor_sync(0xFFFFFFFFu, p1, off);
            p2 += __shfl_xor_sync(0xFFFFFFFFu, p2, off);
            p3 += __shfl_xor_sync(0xFFFFFFFFu, p3, off);
        }
        if (lane == 0) g_V[b * CD + j0 + 0] = (p0 + be[0]) * sj[0];
        if (lane == 1) g_V[b * CD + j0 + 1] = (p1 + be[1]) * sj[1];
        if (lane == 2) g_V[b * CD + j0 + 2] = (p2 + be[2]) * sj[2];
        if (lane == 3) g_V[b * CD + j0 + 3] = (p3 + be[3]) * sj[3];
    }
}

// ---------------------------------------------------------------------------
// K2: (frozen) sx scan + circulant slide (8-slot reg window, FFMA2 over
// o-pairs) + scatter. grid (64, 8 og), 128 threads.
// ---------------------------------------------------------------------------
#define NSLOT 520
__global__ void __launch_bounds__(128, 4)
k2_buildN(const float* __restrict__ conv1_w,
          const int*   __restrict__ h1,
          const int*   __restrict__ h2,
          const float* __restrict__ s2) {
    __shared__ int   h1s[CD];
    __shared__ float vs[CD];
    __shared__ unsigned long long sdup[CD];
    __shared__ unsigned long long wpA[NSLOT];
    __shared__ unsigned long long wpB[NSLOT];
    __shared__ float Msm[CD * 4];

    const int b   = blockIdx.x;
    const int og  = blockIdx.y;
    const int tid = threadIdx.x;

    for (int i = tid; i < CD; i += 128) {
        h1s[i] = h1[i];
        vs[i]  = g_V[b * CD + i];
    }
    {
        const float* w0 = conv1_w + (og * 4 + 0) * CD;
        const float* w1 = conv1_w + (og * 4 + 1) * CD;
        const float* w2 = conv1_w + (og * 4 + 2) * CD;
        const float* w3 = conv1_w + (og * 4 + 3) * CD;
        for (int s = tid; s < NSLOT; s += 128) {
            int sm = s & 255;
            wpA[s] = pack2(w0[sm], w1[sm]);
            wpB[s] = pack2(w2[sm], w3[sm]);
        }
    }
    __syncthreads();

#pragma unroll
    for (int mi = 0; mi < 2; mi++) {
        const int m  = tid + mi * 128;
        float     sv = 0.f;
        const int4*   h4 = (const int4*)h1s;
        const float4* v4 = (const float4*)vs;
#pragma unroll 8
        for (int q = 0; q < CD / 4; q++) {
            int4   h = h4[q];
            float4 v = v4[q];
            if (h.x == m) sv += v.x;
            if (h.y == m) sv += v.y;
            if (h.z == m) sv += v.z;
            if (h.w == m) sv += v.w;
        }
        sdup[m] = pack2(sv, sv);
    }
    __syncthreads();

    const int mq = tid >> 1;
    const int pp = tid & 1;
    const int m0 = mq * 4;
    const unsigned long long* wp = pp ? wpB : wpA;

    unsigned long long w[8];
#pragma unroll
    for (int k = 0; k < 8; k++) w[k] = wp[m0 + k];

    unsigned long long a0 = 0ull, a1 = 0ull, a2 = 0ull, a3 = 0ull;
#pragma unroll 4
    for (int jj = 0; jj < CD; jj += 4) {
        unsigned long long s0  = sdup[jj + 0];
        unsigned long long s1v = sdup[jj + 1];
        unsigned long long s2v = sdup[jj + 2];
        unsigned long long s3v = sdup[jj + 3];
        a0 = fma2(s0, w[0], a0);  a1 = fma2(s0, w[1], a1);
        a2 = fma2(s0, w[2], a2);  a3 = fma2(s0, w[3], a3);
        a0 = fma2(s1v, w[1], a0); a1 = fma2(s1v, w[2], a1);
        a2 = fma2(s1v, w[3], a2); a3 = fma2(s1v, w[4], a3);
        a0 = fma2(s2v, w[2], a0); a1 = fma2(s2v, w[3], a1);
        a2 = fma2(s2v, w[4], a2); a3 = fma2(s2v, w[5], a3);
        a0 = fma2(s3v, w[3], a0); a1 = fma2(s3v, w[4], a1);
        a2 = fma2(s3v, w[5], a2); a3 = fma2(s3v, w[6], a3);
        w[0] = w[4]; w[1] = w[5]; w[2] = w[6]; w[3] = w[7];
        w[4] = wp[m0 + jj + 8];  w[5] = wp[m0 + jj + 9];
        w[6] = wp[m0 + jj + 10]; w[7] = wp[m0 + jj + 11];
    }
    {
        float2 f0 = unpack2(a0), f1 = unpack2(a1), f2 = unpack2(a2), f3 = unpack2(a3);
        Msm[(m0 + 0) * 4 + pp * 2 + 0] = f0.x; Msm[(m0 + 0) * 4 + pp * 2 + 1] = f0.y;
        Msm[(m0 + 1) * 4 + pp * 2 + 0] = f1.x; Msm[(m0 + 1) * 4 + pp * 2 + 1] = f1.y;
        Msm[(m0 + 2) * 4 + pp * 2 + 0] = f2.x; Msm[(m0 + 2) * 4 + pp * 2 + 1] = f2.y;
        Msm[(m0 + 3) * 4 + pp * 2 + 0] = f3.x; Msm[(m0 + 3) * 4 + pp * 2 + 1] = f3.y;
    }
    __syncthreads();

    for (int c = tid; c < CD; c += 128) {
        const int   hc = h2[c];
        const float sc = s2[c];
        float4 mv = *(const float4*)&Msm[hc * 4];
        *(float4*)&g_N[((size_t)b * CD + c) * O1 + og * 4] =
            make_float4(sc * mv.x, sc * mv.y, sc * mv.z, sc * mv.w);
    }
}

// ---------------------------------------------------------------------------
// K3 (frozen, R12): bulk cp.async loads, cg c-split FFMA2 mainloop,
// __stcs streaming stores on the 51 MB write-once attr_feature stream.
// ---------------------------------------------------------------------------
__global__ void __launch_bounds__(128, 2)
k3_fused(const float* __restrict__ ef,
         const float* __restrict__ conv2_w,
         float* __restrict__ out_map,
         float* __restrict__ out_feat) {
    extern __shared__ float smem[];
    float* Xs   = smem;                         // [256][64]
    float* Ns   = Xs + CD * TILE;               // [256][32]
    float* bufF = Ns + CD * O1;                 // 2048 floats
    float* red  = bufF + 2048;                  // [8][65]
    float* amap = red + 8 * 65;                 // [64]

    const int b   = blockIdx.y;
    const int hw0 = blockIdx.x * TILE;
    const int tid = threadIdx.x;

    {
        unsigned int ns_s = (unsigned int)__cvta_generic_to_shared(Ns);
        const float* ng   = g_N + (size_t)b * CD * O1;
#pragma unroll
        for (int i = 0; i < 16; i++) {
            int e4 = tid + i * 128;
            cpa16(ns_s + e4 * 16, ng + e4 * 4);
        }
        unsigned int xs_s = (unsigned int)__cvta_generic_to_shared(Xs);
        const float* efb  = ef + (size_t)b * CD * HWD;
#pragma unroll
        for (int k = 0; k < 32; k++) {
            int idx = tid + k * 128;
            int c   = idx >> 4;
            int t   = (idx & 15) * 4;
            if (hw0 + t < HWD)
                cpa16(xs_s + (c * TILE + t) * 4, efb + (size_t)c * HWD + hw0 + t);
            else
                *(float4*)(Xs + c * TILE + t) = make_float4(0.f, 0.f, 0.f, 0.f);
        }
        cpa_commit_wait();
    }
    __syncthreads();

    const int cg = tid >> 6;
    const int r  = tid & 63;
    const int oo = r & 7;
    const int tt = r >> 3;
    const int c0 = cg * (CD / 2);

    unsigned long long acc[4][4];
#pragma unroll
    for (int i = 0; i < 4; i++)
#pragma unroll
        for (int j = 0; j < 4; j++) acc[i][j] = 0ull;

    const float* xp = Xs + tt * 8;
    const float* np = Ns + oo * 4;
#pragma unroll 4
    for (int cc = 0; cc < CD / 2; cc++) {
        const int c = c0 + cc;
        ulonglong2 xa = *(const ulonglong2*)(xp + c * TILE);
        ulonglong2 xb = *(const ulonglong2*)(xp + c * TILE + 4);
        float4     nv = *(const float4*)(np + c * O1);
        unsigned long long n0 = pack2(nv.x, nv.x);
        unsigned long long n1 = pack2(nv.y, nv.y);
        unsigned long long n2 = pack2(nv.z, nv.z);
        unsigned long long n3 = pack2(nv.w, nv.w);
        acc[0][0] = fma2(n0, xa.x, acc[0][0]); acc[0][1] = fma2(n0, xa.y, acc[0][1]);
        acc[0][2] = fma2(n0, xb.x, acc[0][2]); acc[0][3] = fma2(n0, xb.y, acc[0][3]);
        acc[1][0] = fma2(n1, xa.x, acc[1][0]); acc[1][1] = fma2(n1, xa.y, acc[1][1]);
        acc[1][2] = fma2(n1, xb.x, acc[1][2]); acc[1][3] = fma2(n1, xb.y, acc[1][3]);
        acc[2][0] = fma2(n2, xa.x, acc[2][0]); acc[2][1] = fma2(n2, xa.y, acc[2][1]);
        acc[2][2] = fma2(n2, xb.x, acc[2][2]); acc[2][3] = fma2(n2, xb.y, acc[2][3]);
        acc[3][0] = fma2(n3, xa.x, acc[3][0]); acc[3][1] = fma2(n3, xa.y, acc[3][1]);
        acc[3][2] = fma2(n3, xb.x, acc[3][2]); acc[3][3] = fma2(n3, xb.y, acc[3][3]);
    }

    unsigned long long* buf = (unsigned long long*)bufF;
    if (cg == 1) {
#pragma unroll
        for (int i = 0; i < 4; i++)
#pragma unroll
            for (int j = 0; j < 4; j++)
                buf[(i * 4 + j) * 64 + r] = acc[i][j];
    }
    __syncthreads();
    if (cg == 0) {
        float p[8] = {0.f, 0.f, 0.f, 0.f, 0.f, 0.f, 0.f, 0.f};
#pragma unroll
        for (int i = 0; i < 4; i++) {
            float cw = __ldg(conv2_w + oo * 4 + i);
#pragma unroll
            for (int j = 0; j < 4; j++) {
                unsigned long long t2 = add2(acc[i][j], buf[(i * 4 + j) * 64 + r]);
                float2 f = unpack2(t2);
                p[2 * j]     += cw * fmaxf(f.x, 0.f);
                p[2 * j + 1] += cw * fmaxf(f.y, 0.f);
            }
        }
#pragma unroll
        for (int k = 0; k < 8; k++) red[oo * 65 + tt * 8 + k] = p[k];
    }
    __syncthreads();

    if (tid < TILE) {
        float s = 0.f;
#pragma unroll
        for (int g = 0; g < 8; g++) s += red[g * 65 + tid];
        float am = 1.f / (1.f + expf(-s));
        amap[tid] = am;
        if (hw0 + tid < HWD) out_map[b * HWD + hw0 + tid] = am;
    }
    __syncthreads();

    float* ofb = out_feat + (size_t)b * CD * HWD;
#pragma unroll
    for (int k = 0; k < 32; k++) {
        int idx = tid + k * 128;
        int c   = idx >> 4;
        int t   = (idx & 15) * 4;
        if (hw0 + t < HWD) {
            float4 v  = *(const float4*)(Xs + c * TILE + t);
            float  a0 = amap[t],     a1 = amap[t + 1];
            float  a2 = amap[t + 2], a3 = amap[t + 3];
            __stcs((float4*)(ofb + (size_t)c * HWD + hw0 + t),
                   make_float4(v.x * a0, v.y * a1, v.z * a2, v.w * a3));
        }
    }
}

// ---------------------------------------------------------------------------
extern "C" void kernel_launch(void* const* d_in, const int* in_sizes, int n_in,
                              void* d_out, int out_size) {
    const float* entity  = (const float*)d_in[0];
    const float* attr1h  = (const float*)d_in[1];
    const float* W_emb   = (const float*)d_in[2];
    const float* b_emb   = (const float*)d_in[3];
    const int*   h1      = (const int*)  d_in[4];
    const float* s1      = (const float*)d_in[5];
    const int*   h2      = (const int*)  d_in[6];
    const float* s2      = (const float*)d_in[7];
    const float* conv1_w = (const float*)d_in[8];
    const float* conv2_w = (const float*)d_in[9];

    float* out_map  = (float*)d_out;
    float* out_feat = (float*)d_out + (size_t)BD * HWD;

    const int k3_smem = (CD * TILE + CD * O1 + 2048 + 8 * 65 + TILE) * (int)sizeof(float);
    cudaFuncSetAttribute(k3_fused, cudaFuncAttributeMaxDynamicSharedMemorySize, k3_smem);

    k1_emb<<<dim3(8, BD / BG), 256>>>(attr1h, W_emb, b_emb, s1);
    k2_buildN<<<dim3(BD, 8), 128>>>(conv1_w, h1, h2, s2);
    k3_fused<<<dim3((HWD + TILE - 1) / TILE, BD), 128, k3_smem>>>(entity, conv2_w, out_map, out_feat);
}

// round 14
// speedup vs baseline: 1.0418x; 1.0418x over previous
#include <cuda_runtime.h>
#include <math.h>

#define BD   64
#define CD   256
#define ATTR 300
#define HWD  784
#define O1   32
#define TILE 64

__device__ float g_V[BD * CD];           // v[b][j] = s1[j] * emb[b][j]
__device__ float g_N[BD * CD * O1];      // folded [b][c][o] matrix

// ---- f32x2 packed helpers ---------------------------------------------------
__device__ __forceinline__ unsigned long long pack2(float a, float b) {
    unsigned long long r;
    asm("mov.b64 %0, {%1, %2};" : "=l"(r)
        : "r"(__float_as_uint(a)), "r"(__float_as_uint(b)));
    return r;
}
__device__ __forceinline__ unsigned long long fma2(unsigned long long a,
                                                   unsigned long long b,
                                                   unsigned long long c) {
    unsigned long long d;
    asm("fma.rn.f32x2 %0, %1, %2, %3;" : "=l"(d) : "l"(a), "l"(b), "l"(c));
    return d;
}
__device__ __forceinline__ unsigned long long add2(unsigned long long a,
                                                   unsigned long long b) {
    unsigned long long d;
    asm("add.rn.f32x2 %0, %1, %2;" : "=l"(d) : "l"(a), "l"(b));
    return d;
}
__device__ __forceinline__ float2 unpack2(unsigned long long v) {
    float2 f;
    f.x = __uint_as_float((unsigned)v);
    f.y = __uint_as_float((unsigned)(v >> 32));
    return f;
}
// ---- cp.async helpers -------------------------------------------------------
__device__ __forceinline__ void cpa16(unsigned int dst_smem, const void* src) {
    asm volatile("cp.async.cg.shared.global [%0], [%1], 16;"
                 :: "r"(dst_smem), "l"(src));
}
// evict-first L2 policy for read-once streams
__device__ __forceinline__ void cpa16_stream(unsigned int dst_smem, const void* src) {
    asm volatile(
        "{\n\t"
        ".reg .b64 pol;\n\t"
        "createpolicy.fractional.L2::evict_first.b64 pol, 1.0;\n\t"
        "cp.async.cg.shared.global.L2::cache_hint [%0], [%1], 16, pol;\n\t"
        "}"
        :: "r"(dst_smem), "l"(src));
}
__device__ __forceinline__ void cpa_commit_wait() {
    asm volatile("cp.async.commit_group;");
    asm volatile("cp.async.wait_group 0;" ::: "memory");
}

// ---------------------------------------------------------------------------
// K1 (R12 frozen): v[b,j] = s1[j] * (attr_one_hot[b] . W_emb[j] + b_emb[j])
// grid (64, 8 jg), 256 threads; each warp one quad of j's, 40 batched LDGs.
// ---------------------------------------------------------------------------
__global__ void __launch_bounds__(256, 4)
k1_emb(const float* __restrict__ attr_one_hot,
       const float* __restrict__ W_emb,
       const float* __restrict__ b_emb,
       const float* __restrict__ s1) {
    __shared__ float attr_sm[ATTR];

    const int b    = blockIdx.x;
    const int jg   = blockIdx.y;
    const int tid  = threadIdx.x;
    const int lane = tid & 31;
    const int wrp  = tid >> 5;

    for (int a = tid; a < ATTR; a += 256) attr_sm[a] = attr_one_hot[b * ATTR + a];
    __syncthreads();

    const int j0 = jg * 32 + wrp * 4;
    float wv[4][10];
#pragma unroll
    for (int k = 0; k < 10; k++) {
        const int  a  = lane + 32 * k;
        const bool ok = (a < ATTR);
#pragma unroll
        for (int q = 0; q < 4; q++)
            wv[q][k] = ok ? W_emb[(size_t)(j0 + q) * ATTR + a] : 0.f;
    }
    float p0 = 0.f, p1 = 0.f, p2 = 0.f, p3 = 0.f;
#pragma unroll
    for (int k = 0; k < 10; k++) {
        const int   a  = lane + 32 * k;
        const float av = (a < ATTR) ? attr_sm[a] : 0.f;
        p0 += av * wv[0][k];
        p1 += av * wv[1][k];
        p2 += av * wv[2][k];
        p3 += av * wv[3][k];
    }
#pragma unroll
    for (int off = 16; off >= 1; off >>= 1) {
        p0 += __shfl_xor_sync(0xFFFFFFFFu, p0, off);
        p1 += __shfl_xor_sync(0xFFFFFFFFu, p1, off);
        p2 += __shfl_xor_sync(0xFFFFFFFFu, p2, off);
        p3 += __shfl_xor_sync(0xFFFFFFFFu, p3, off);
    }
    if (lane == 0) g_V[b * CD + j0 + 0] = (p0 + b_emb[j0 + 0]) * s1[j0 + 0];
    if (lane == 1) g_V[b * CD + j0 + 1] = (p1 + b_emb[j0 + 1]) * s1[j0 + 1];
    if (lane == 2) g_V[b * CD + j0 + 2] = (p2 + b_emb[j0 + 2]) * s1[j0 + 2];
    if (lane == 3) g_V[b * CD + j0 + 3] = (p3 + b_emb[j0 + 3]) * s1[j0 + 3];
}

// ---------------------------------------------------------------------------
// K2: (frozen) sx scan + circulant slide (8-slot reg window, FFMA2 over
// o-pairs) + scatter. grid (64, 8 og), 128 threads.
// ---------------------------------------------------------------------------
#define NSLOT 520
__global__ void __launch_bounds__(128, 4)
k2_buildN(const float* __restrict__ conv1_w,
          const int*   __restrict__ h1,
          const int*   __restrict__ h2,
          const float* __restrict__ s2) {
    __shared__ int   h1s[CD];
    __shared__ float vs[CD];
    __shared__ unsigned long long sdup[CD];
    __shared__ unsigned long long wpA[NSLOT];
    __shared__ unsigned long long wpB[NSLOT];
    __shared__ float Msm[CD * 4];

    const int b   = blockIdx.x;
    const int og  = blockIdx.y;
    const int tid = threadIdx.x;

    for (int i = tid; i < CD; i += 128) {
        h1s[i] = h1[i];
        vs[i]  = g_V[b * CD + i];
    }
    {
        const float* w0 = conv1_w + (og * 4 + 0) * CD;
        const float* w1 = conv1_w + (og * 4 + 1) * CD;
        const float* w2 = conv1_w + (og * 4 + 2) * CD;
        const float* w3 = conv1_w + (og * 4 + 3) * CD;
        for (int s = tid; s < NSLOT; s += 128) {
            int sm = s & 255;
            wpA[s] = pack2(w0[sm], w1[sm]);
            wpB[s] = pack2(w2[sm], w3[sm]);
        }
    }
    __syncthreads();

#pragma unroll
    for (int mi = 0; mi < 2; mi++) {
        const int m  = tid + mi * 128;
        float     sv = 0.f;
        const int4*   h4 = (const int4*)h1s;
        const float4* v4 = (const float4*)vs;
#pragma unroll 8
        for (int q = 0; q < CD / 4; q++) {
            int4   h = h4[q];
            float4 v = v4[q];
            if (h.x == m) sv += v.x;
            if (h.y == m) sv += v.y;
            if (h.z == m) sv += v.z;
            if (h.w == m) sv += v.w;
        }
        sdup[m] = pack2(sv, sv);
    }
    __syncthreads();

    const int mq = tid >> 1;
    const int pp = tid & 1;
    const int m0 = mq * 4;
    const unsigned long long* wp = pp ? wpB : wpA;

    unsigned long long w[8];
#pragma unroll
    for (int k = 0; k < 8; k++) w[k] = wp[m0 + k];

    unsigned long long a0 = 0ull, a1 = 0ull, a2 = 0ull, a3 = 0ull;
#pragma unroll 4
    for (int jj = 0; jj < CD; jj += 4) {
        unsigned long long s0  = sdup[jj + 0];
        unsigned long long s1v = sdup[jj + 1];
        unsigned long long s2v = sdup[jj + 2];
        unsigned long long s3v = sdup[jj + 3];
        a0 = fma2(s0, w[0], a0);  a1 = fma2(s0, w[1], a1);
        a2 = fma2(s0, w[2], a2);  a3 = fma2(s0, w[3], a3);
        a0 = fma2(s1v, w[1], a0); a1 = fma2(s1v, w[2], a1);
        a2 = fma2(s1v, w[3], a2); a3 = fma2(s1v, w[4], a3);
        a0 = fma2(s2v, w[2], a0); a1 = fma2(s2v, w[3], a1);
        a2 = fma2(s2v, w[4], a2); a3 = fma2(s2v, w[5], a3);
        a0 = fma2(s3v, w[3], a0); a1 = fma2(s3v, w[4], a1);
        a2 = fma2(s3v, w[5], a2); a3 = fma2(s3v, w[6], a3);
        w[0] = w[4]; w[1] = w[5]; w[2] = w[6]; w[3] = w[7];
        w[4] = wp[m0 + jj + 8];  w[5] = wp[m0 + jj + 9];
        w[6] = wp[m0 + jj + 10]; w[7] = wp[m0 + jj + 11];
    }
    {
        float2 f0 = unpack2(a0), f1 = unpack2(a1), f2 = unpack2(a2), f3 = unpack2(a3);
        Msm[(m0 + 0) * 4 + pp * 2 + 0] = f0.x; Msm[(m0 + 0) * 4 + pp * 2 + 1] = f0.y;
        Msm[(m0 + 1) * 4 + pp * 2 + 0] = f1.x; Msm[(m0 + 1) * 4 + pp * 2 + 1] = f1.y;
        Msm[(m0 + 2) * 4 + pp * 2 + 0] = f2.x; Msm[(m0 + 2) * 4 + pp * 2 + 1] = f2.y;
        Msm[(m0 + 3) * 4 + pp * 2 + 0] = f3.x; Msm[(m0 + 3) * 4 + pp * 2 + 1] = f3.y;
    }
    __syncthreads();

    for (int c = tid; c < CD; c += 128) {
        const int   hc = h2[c];
        const float sc = s2[c];
        float4 mv = *(const float4*)&Msm[hc * 4];
        *(float4*)&g_N[((size_t)b * CD + c) * O1 + og * 4] =
            make_float4(sc * mv.x, sc * mv.y, sc * mv.z, sc * mv.w);
    }
}

// ---------------------------------------------------------------------------
// K3 (R12 + streaming READS): bulk cp.async loads (X stream = evict_first,
// N = evict_normal so hot matrices stay in L2), cg c-split FFMA2 mainloop,
// __stcs streaming stores on the write-once attr_feature stream.
// ---------------------------------------------------------------------------
__global__ void __launch_bounds__(128, 2)
k3_fused(const float* __restrict__ ef,
         const float* __restrict__ conv2_w,
         float* __restrict__ out_map,
         float* __restrict__ out_feat) {
    extern __shared__ float smem[];
    float* Xs   = smem;                         // [256][64]
    float* Ns   = Xs + CD * TILE;               // [256][32]
    float* bufF = Ns + CD * O1;                 // 2048 floats
    float* red  = bufF + 2048;                  // [8][65]
    float* amap = red + 8 * 65;                 // [64]

    const int b   = blockIdx.y;
    const int hw0 = blockIdx.x * TILE;
    const int tid = threadIdx.x;

    {
        unsigned int ns_s = (unsigned int)__cvta_generic_to_shared(Ns);
        const float* ng   = g_N + (size_t)b * CD * O1;
#pragma unroll
        for (int i = 0; i < 16; i++) {
            int e4 = tid + i * 128;
            cpa16(ns_s + e4 * 16, ng + e4 * 4);          // N: keep in L2
        }
        unsigned int xs_s = (unsigned int)__cvta_generic_to_shared(Xs);
        const float* efb  = ef + (size_t)b * CD * HWD;
#pragma unroll
        for (int k = 0; k < 32; k++) {
            int idx = tid + k * 128;
            int c   = idx >> 4;
            int t   = (idx & 15) * 4;
            if (hw0 + t < HWD)
                cpa16_stream(xs_s + (c * TILE + t) * 4,   // X: read-once stream
                             efb + (size_t)c * HWD + hw0 + t);
            else
                *(float4*)(Xs + c * TILE + t) = make_float4(0.f, 0.f, 0.f, 0.f);
        }
        cpa_commit_wait();
    }
    __syncthreads();

    const int cg = tid >> 6;
    const int r  = tid & 63;
    const int oo = r & 7;
    const int tt = r >> 3;
    const int c0 = cg * (CD / 2);

    unsigned long long acc[4][4];
#pragma unroll
    for (int i = 0; i < 4; i++)
#pragma unroll
        for (int j = 0; j < 4; j++) acc[i][j] = 0ull;

    const float* xp = Xs + tt * 8;
    const float* np = Ns + oo * 4;
#pragma unroll 4
    for (int cc = 0; cc < CD / 2; cc++) {
        const int c = c0 + cc;
        ulonglong2 xa = *(const ulonglong2*)(xp + c * TILE);
        ulonglong2 xb = *(const ulonglong2*)(xp + c * TILE + 4);
        float4     nv = *(const float4*)(np + c * O1);
        unsigned long long n0 = pack2(nv.x, nv.x);
        unsigned long long n1 = pack2(nv.y, nv.y);
        unsigned long long n2 = pack2(nv.z, nv.z);
        unsigned long long n3 = pack2(nv.w, nv.w);
        acc[0][0] = fma2(n0, xa.x, acc[0][0]); acc[0][1] = fma2(n0, xa.y, acc[0][1]);
        acc[0][2] = fma2(n0, xb.x, acc[0][2]); acc[0][3] = fma2(n0, xb.y, acc[0][3]);
        acc[1][0] = fma2(n1, xa.x, acc[1][0]); acc[1][1] = fma2(n1, xa.y, acc[1][1]);
        acc[1][2] = fma2(n1, xb.x, acc[1][2]); acc[1][3] = fma2(n1, xb.y, acc[1][3]);
        acc[2][0] = fma2(n2, xa.x, acc[2][0]); acc[2][1] = fma2(n2, xa.y, acc[2][1]);
        acc[2][2] = fma2(n2, xb.x, acc[2][2]); acc[2][3] = fma2(n2, xb.y, acc[2][3]);
        acc[3][0] = fma2(n3, xa.x, acc[3][0]); acc[3][1] = fma2(n3, xa.y, acc[3][1]);
        acc[3][2] = fma2(n3, xb.x, acc[3][2]); acc[3][3] = fma2(n3, xb.y, acc[3][3]);
    }

    unsigned long long* buf = (unsigned long long*)bufF;
    if (cg == 1) {
#pragma unroll
        for (int i = 0; i < 4; i++)
#pragma unroll
            for (int j = 0; j < 4; j++)
                buf[(i * 4 + j) * 64 + r] = acc[i][j];
    }
    __syncthreads();
    if (cg == 0) {
        float p[8] = {0.f, 0.f, 0.f, 0.f, 0.f, 0.f, 0.f, 0.f};
#pragma unroll
        for (int i = 0; i < 4; i++) {
            float cw = __ldg(conv2_w + oo * 4 + i);
#pragma unroll
            for (int j = 0; j < 4; j++) {
                unsigned long long t2 = add2(acc[i][j], buf[(i * 4 + j) * 64 + r]);
                float2 f = unpack2(t2);
                p[2 * j]     += cw * fmaxf(f.x, 0.f);
                p[2 * j + 1] += cw * fmaxf(f.y, 0.f);
            }
        }
#pragma unroll
        for (int k = 0; k < 8; k++) red[oo * 65 + tt * 8 + k] = p[k];
    }
    __syncthreads();

    if (tid < TILE) {
        float s = 0.f;
#pragma unroll
        for (int g = 0; g < 8; g++) s += red[g * 65 + tid];
        float am = 1.f / (1.f + expf(-s));
        amap[tid] = am;
        if (hw0 + tid < HWD) out_map[b * HWD + hw0 + tid] = am;
    }
    __syncthreads();

    float* ofb = out_feat + (size_t)b * CD * HWD;
#pragma unroll
    for (int k = 0; k < 32; k++) {
        int idx = tid + k * 128;
        int c   = idx >> 4;
        int t   = (idx & 15) * 4;
        if (hw0 + t < HWD) {
            float4 v  = *(const float4*)(Xs + c * TILE + t);
            float  a0 = amap[t],     a1 = amap[t + 1];
            float  a2 = amap[t + 2], a3 = amap[t + 3];
            __stcs((float4*)(ofb + (size_t)c * HWD + hw0 + t),
                   make_float4(v.x * a0, v.y * a1, v.z * a2, v.w * a3));
        }
    }
}

// ---------------------------------------------------------------------------
extern "C" void kernel_launch(void* const* d_in, const int* in_sizes, int n_in,
                              void* d_out, int out_size) {
    const float* entity  = (const float*)d_in[0];
    const float* attr1h  = (const float*)d_in[1];
    const float* W_emb   = (const float*)d_in[2];
    const float* b_emb   = (const float*)d_in[3];
    const int*   h1      = (const int*)  d_in[4];
    const float* s1      = (const float*)d_in[5];
    const int*   h2      = (const int*)  d_in[6];
    const float* s2      = (const float*)d_in[7];
    const float* conv1_w = (const float*)d_in[8];
    const float* conv2_w = (const float*)d_in[9];

    float* out_map  = (float*)d_out;
    float* out_feat = (float*)d_out + (size_t)BD * HWD;

    const int k3_smem = (CD * TILE + CD * O1 + 2048 + 8 * 65 + TILE) * (int)sizeof(float);
    cudaFuncSetAttribute(k3_fused, cudaFuncAttributeMaxDynamicSharedMemorySize, k3_smem);

    k1_emb<<<dim3(BD, 8), 256>>>(attr1h, W_emb, b_emb, s1);
    k2_buildN<<<dim3(BD, 8), 128>>>(conv1_w, h1, h2, s2);
    k3_fused<<<dim3((HWD + TILE - 1) / TILE, BD), 128, k3_smem>>>(entity, conv2_w, out_map, out_feat);
}

// round 15
// speedup vs baseline: 1.0680x; 1.0251x over previous
#include <cuda_runtime.h>
#include <math.h>

#define BD   64
#define CD   256
#define ATTR 300
#define HWD  784
#define O1   32
#define TILE 64

__device__ float g_V[BD * CD];           // v[b][j] = s1[j] * emb[b][j]
__device__ float g_N[BD * CD * O1];      // folded [b][c][o] matrix

// ---- f32x2 packed helpers ---------------------------------------------------
__device__ __forceinline__ unsigned long long pack2(float a, float b) {
    unsigned long long r;
    asm("mov.b64 %0, {%1, %2};" : "=l"(r)
        : "r"(__float_as_uint(a)), "r"(__float_as_uint(b)));
    return r;
}
__device__ __forceinline__ unsigned long long fma2(unsigned long long a,
                                                   unsigned long long b,
                                                   unsigned long long c) {
    unsigned long long d;
    asm("fma.rn.f32x2 %0, %1, %2, %3;" : "=l"(d) : "l"(a), "l"(b), "l"(c));
    return d;
}
__device__ __forceinline__ unsigned long long add2(unsigned long long a,
                                                   unsigned long long b) {
    unsigned long long d;
    asm("add.rn.f32x2 %0, %1, %2;" : "=l"(d) : "l"(a), "l"(b));
    return d;
}
__device__ __forceinline__ float2 unpack2(unsigned long long v) {
    float2 f;
    f.x = __uint_as_float((unsigned)v);
    f.y = __uint_as_float((unsigned)(v >> 32));
    return f;
}
// ---- cp.async helpers -------------------------------------------------------
__device__ __forceinline__ void cpa16(unsigned int dst_smem, const void* src) {
    asm volatile("cp.async.cg.shared.global [%0], [%1], 16;"
                 :: "r"(dst_smem), "l"(src));
}
__device__ __forceinline__ void cpa_commit_wait() {
    asm volatile("cp.async.commit_group;");
    asm volatile("cp.async.wait_group 0;" ::: "memory");
}

// ---------------------------------------------------------------------------
// K1 (frozen): v[b,j] = s1[j] * (attr_one_hot[b] . W_emb[j] + b_emb[j])
// grid (64, 8 jg), 256 threads; each warp one quad of j's, 40 batched LDGs.
// ---------------------------------------------------------------------------
__global__ void __launch_bounds__(256, 4)
k1_emb(const float* __restrict__ attr_one_hot,
       const float* __restrict__ W_emb,
       const float* __restrict__ b_emb,
       const float* __restrict__ s1) {
    __shared__ float attr_sm[ATTR];

    const int b    = blockIdx.x;
    const int jg   = blockIdx.y;
    const int tid  = threadIdx.x;
    const int lane = tid & 31;
    const int wrp  = tid >> 5;

    for (int a = tid; a < ATTR; a += 256) attr_sm[a] = attr_one_hot[b * ATTR + a];
    __syncthreads();

    const int j0 = jg * 32 + wrp * 4;
    float wv[4][10];
#pragma unroll
    for (int k = 0; k < 10; k++) {
        const int  a  = lane + 32 * k;
        const bool ok = (a < ATTR);
#pragma unroll
        for (int q = 0; q < 4; q++)
            wv[q][k] = ok ? W_emb[(size_t)(j0 + q) * ATTR + a] : 0.f;
    }
    float p0 = 0.f, p1 = 0.f, p2 = 0.f, p3 = 0.f;
#pragma unroll
    for (int k = 0; k < 10; k++) {
        const int   a  = lane + 32 * k;
        const float av = (a < ATTR) ? attr_sm[a] : 0.f;
        p0 += av * wv[0][k];
        p1 += av * wv[1][k];
        p2 += av * wv[2][k];
        p3 += av * wv[3][k];
    }
#pragma unroll
    for (int off = 16; off >= 1; off >>= 1) {
        p0 += __shfl_xor_sync(0xFFFFFFFFu, p0, off);
        p1 += __shfl_xor_sync(0xFFFFFFFFu, p1, off);
        p2 += __shfl_xor_sync(0xFFFFFFFFu, p2, off);
        p3 += __shfl_xor_sync(0xFFFFFFFFu, p3, off);
    }
    if (lane == 0) g_V[b * CD + j0 + 0] = (p0 + b_emb[j0 + 0]) * s1[j0 + 0];
    if (lane == 1) g_V[b * CD + j0 + 1] = (p1 + b_emb[j0 + 1]) * s1[j0 + 1];
    if (lane == 2) g_V[b * CD + j0 + 2] = (p2 + b_emb[j0 + 2]) * s1[j0 + 2];
    if (lane == 3) g_V[b * CD + j0 + 3] = (p3 + b_emb[j0 + 3]) * s1[j0 + 3];
}

// ---------------------------------------------------------------------------
// K2 (frozen): sx scan + circulant slide (8-slot reg window, FFMA2 over
// o-pairs) + scatter. grid (64, 8 og), 128 threads.
// ---------------------------------------------------------------------------
#define NSLOT 520
__global__ void __launch_bounds__(128, 4)
k2_buildN(const float* __restrict__ conv1_w,
          const int*   __restrict__ h1,
          const int*   __restrict__ h2,
          const float* __restrict__ s2) {
    __shared__ int   h1s[CD];
    __shared__ float vs[CD];
    __shared__ unsigned long long sdup[CD];
    __shared__ unsigned long long wpA[NSLOT];
    __shared__ unsigned long long wpB[NSLOT];
    __shared__ float Msm[CD * 4];

    const int b   = blockIdx.x;
    const int og  = blockIdx.y;
    const int tid = threadIdx.x;

    for (int i = tid; i < CD; i += 128) {
        h1s[i] = h1[i];
        vs[i]  = g_V[b * CD + i];
    }
    {
        const float* w0 = conv1_w + (og * 4 + 0) * CD;
        const float* w1 = conv1_w + (og * 4 + 1) * CD;
        const float* w2 = conv1_w + (og * 4 + 2) * CD;
        const float* w3 = conv1_w + (og * 4 + 3) * CD;
        for (int s = tid; s < NSLOT; s += 128) {
            int sm = s & 255;
            wpA[s] = pack2(w0[sm], w1[sm]);
            wpB[s] = pack2(w2[sm], w3[sm]);
        }
    }
    __syncthreads();

#pragma unroll
    for (int mi = 0; mi < 2; mi++) {
        const int m  = tid + mi * 128;
        float     sv = 0.f;
        const int4*   h4 = (const int4*)h1s;
        const float4* v4 = (const float4*)vs;
#pragma unroll 8
        for (int q = 0; q < CD / 4; q++) {
            int4   h = h4[q];
            float4 v = v4[q];
            if (h.x == m) sv += v.x;
            if (h.y == m) sv += v.y;
            if (h.z == m) sv += v.z;
            if (h.w == m) sv += v.w;
        }
        sdup[m] = pack2(sv, sv);
    }
    __syncthreads();

    const int mq = tid >> 1;
    const int pp = tid & 1;
    const int m0 = mq * 4;
    const unsigned long long* wp = pp ? wpB : wpA;

    unsigned long long w[8];
#pragma unroll
    for (int k = 0; k < 8; k++) w[k] = wp[m0 + k];

    unsigned long long a0 = 0ull, a1 = 0ull, a2 = 0ull, a3 = 0ull;
#pragma unroll 4
    for (int jj = 0; jj < CD; jj += 4) {
        unsigned long long s0  = sdup[jj + 0];
        unsigned long long s1v = sdup[jj + 1];
        unsigned long long s2v = sdup[jj + 2];
        unsigned long long s3v = sdup[jj + 3];
        a0 = fma2(s0, w[0], a0);  a1 = fma2(s0, w[1], a1);
        a2 = fma2(s0, w[2], a2);  a3 = fma2(s0, w[3], a3);
        a0 = fma2(s1v, w[1], a0); a1 = fma2(s1v, w[2], a1);
        a2 = fma2(s1v, w[3], a2); a3 = fma2(s1v, w[4], a3);
        a0 = fma2(s2v, w[2], a0); a1 = fma2(s2v, w[3], a1);
        a2 = fma2(s2v, w[4], a2); a3 = fma2(s2v, w[5], a3);
        a0 = fma2(s3v, w[3], a0); a1 = fma2(s3v, w[4], a1);
        a2 = fma2(s3v, w[5], a2); a3 = fma2(s3v, w[6], a3);
        w[0] = w[4]; w[1] = w[5]; w[2] = w[6]; w[3] = w[7];
        w[4] = wp[m0 + jj + 8];  w[5] = wp[m0 + jj + 9];
        w[6] = wp[m0 + jj + 10]; w[7] = wp[m0 + jj + 11];
    }
    {
        float2 f0 = unpack2(a0), f1 = unpack2(a1), f2 = unpack2(a2), f3 = unpack2(a3);
        Msm[(m0 + 0) * 4 + pp * 2 + 0] = f0.x; Msm[(m0 + 0) * 4 + pp * 2 + 1] = f0.y;
        Msm[(m0 + 1) * 4 + pp * 2 + 0] = f1.x; Msm[(m0 + 1) * 4 + pp * 2 + 1] = f1.y;
        Msm[(m0 + 2) * 4 + pp * 2 + 0] = f2.x; Msm[(m0 + 2) * 4 + pp * 2 + 1] = f2.y;
        Msm[(m0 + 3) * 4 + pp * 2 + 0] = f3.x; Msm[(m0 + 3) * 4 + pp * 2 + 1] = f3.y;
    }
    __syncthreads();

    for (int c = tid; c < CD; c += 128) {
        const int   hc = h2[c];
        const float sc = s2[c];
        float4 mv = *(const float4*)&Msm[hc * 4];
        *(float4*)&g_N[((size_t)b * CD + c) * O1 + og * 4] =
            make_float4(sc * mv.x, sc * mv.y, sc * mv.z, sc * mv.w);
    }
}

// ---------------------------------------------------------------------------
// K3 (R12 frozen — best config): bulk cp.async loads (default policy),
// cg c-split FFMA2 mainloop, __stcs streaming stores on the 51 MB
// write-once attr_feature stream.
// ---------------------------------------------------------------------------
__global__ void __launch_bounds__(128, 2)
k3_fused(const float* __restrict__ ef,
         const float* __restrict__ conv2_w,
         float* __restrict__ out_map,
         float* __restrict__ out_feat) {
    extern __shared__ float smem[];
    float* Xs   = smem;                         // [256][64]
    float* Ns   = Xs + CD * TILE;               // [256][32]
    float* bufF = Ns + CD * O1;                 // 2048 floats
    float* red  = bufF + 2048;                  // [8][65]
    float* amap = red + 8 * 65;                 // [64]

    const int b   = blockIdx.y;
    const int hw0 = blockIdx.x * TILE;
    const int tid = threadIdx.x;

    {
        unsigned int ns_s = (unsigned int)__cvta_generic_to_shared(Ns);
        const float* ng   = g_N + (size_t)b * CD * O1;
#pragma unroll
        for (int i = 0; i < 16; i++) {
            int e4 = tid + i * 128;
            cpa16(ns_s + e4 * 16, ng + e4 * 4);
        }
        unsigned int xs_s = (unsigned int)__cvta_generic_to_shared(Xs);
        const float* efb  = ef + (size_t)b * CD * HWD;
#pragma unroll
        for (int k = 0; k < 32; k++) {
            int idx = tid + k * 128;
            int c   = idx >> 4;
            int t   = (idx & 15) * 4;
            if (hw0 + t < HWD)
                cpa16(xs_s + (c * TILE + t) * 4, efb + (size_t)c * HWD + hw0 + t);
            else
                *(float4*)(Xs + c * TILE + t) = make_float4(0.f, 0.f, 0.f, 0.f);
        }
        cpa_commit_wait();
    }
    __syncthreads();

    const int cg = tid >> 6;
    const int r  = tid & 63;
    const int oo = r & 7;
    const int tt = r >> 3;
    const int c0 = cg * (CD / 2);

    unsigned long long acc[4][4];
#pragma unroll
    for (int i = 0; i < 4; i++)
#pragma unroll
        for (int j = 0; j < 4; j++) acc[i][j] = 0ull;

    const float* xp = Xs + tt * 8;
    const float* np = Ns + oo * 4;
#pragma unroll 4
    for (int cc = 0; cc < CD / 2; cc++) {
        const int c = c0 + cc;
        ulonglong2 xa = *(const ulonglong2*)(xp + c * TILE);
        ulonglong2 xb = *(const ulonglong2*)(xp + c * TILE + 4);
        float4     nv = *(const float4*)(np + c * O1);
        unsigned long long n0 = pack2(nv.x, nv.x);
        unsigned long long n1 = pack2(nv.y, nv.y);
        unsigned long long n2 = pack2(nv.z, nv.z);
        unsigned long long n3 = pack2(nv.w, nv.w);
        acc[0][0] = fma2(n0, xa.x, acc[0][0]); acc[0][1] = fma2(n0, xa.y, acc[0][1]);
        acc[0][2] = fma2(n0, xb.x, acc[0][2]); acc[0][3] = fma2(n0, xb.y, acc[0][3]);
        acc[1][0] = fma2(n1, xa.x, acc[1][0]); acc[1][1] = fma2(n1, xa.y, acc[1][1]);
        acc[1][2] = fma2(n1, xb.x, acc[1][2]); acc[1][3] = fma2(n1, xb.y, acc[1][3]);
        acc[2][0] = fma2(n2, xa.x, acc[2][0]); acc[2][1] = fma2(n2, xa.y, acc[2][1]);
        acc[2][2] = fma2(n2, xb.x, acc[2][2]); acc[2][3] = fma2(n2, xb.y, acc[2][3]);
        acc[3][0] = fma2(n3, xa.x, acc[3][0]); acc[3][1] = fma2(n3, xa.y, acc[3][1]);
        acc[3][2] = fma2(n3, xb.x, acc[3][2]); acc[3][3] = fma2(n3, xb.y, acc[3][3]);
    }

    unsigned long long* buf = (unsigned long long*)bufF;
    if (cg == 1) {
#pragma unroll
        for (int i = 0; i < 4; i++)
#pragma unroll
            for (int j = 0; j < 4; j++)
                buf[(i * 4 + j) * 64 + r] = acc[i][j];
    }
    __syncthreads();
    if (cg == 0) {
        float p[8] = {0.f, 0.f, 0.f, 0.f, 0.f, 0.f, 0.f, 0.f};
#pragma unroll
        for (int i = 0; i < 4; i++) {
            float cw = __ldg(conv2_w + oo * 4 + i);
#pragma unroll
            for (int j = 0; j < 4; j++) {
                unsigned long long t2 = add2(acc[i][j], buf[(i * 4 + j) * 64 + r]);
                float2 f = unpack2(t2);
                p[2 * j]     += cw * fmaxf(f.x, 0.f);
                p[2 * j + 1] += cw * fmaxf(f.y, 0.f);
            }
        }
#pragma unroll
        for (int k = 0; k < 8; k++) red[oo * 65 + tt * 8 + k] = p[k];
    }
    __syncthreads();

    if (tid < TILE) {
        float s = 0.f;
#pragma unroll
        for (int g = 0; g < 8; g++) s += red[g * 65 + tid];
        float am = 1.f / (1.f + expf(-s));
        amap[tid] = am;
        if (hw0 + tid < HWD) out_map[b * HWD + hw0 + tid] = am;
    }
    __syncthreads();

    float* ofb = out_feat + (size_t)b * CD * HWD;
#pragma unroll
    for (int k = 0; k < 32; k++) {
        int idx = tid + k * 128;
        int c   = idx >> 4;
        int t   = (idx & 15) * 4;
        if (hw0 + t < HWD) {
            float4 v  = *(const float4*)(Xs + c * TILE + t);
            float  a0 = amap[t],     a1 = amap[t + 1];
            float  a2 = amap[t + 2], a3 = amap[t + 3];
            __stcs((float4*)(ofb + (size_t)c * HWD + hw0 + t),
                   make_float4(v.x * a0, v.y * a1, v.z * a2, v.w * a3));
        }
    }
}

// ---------------------------------------------------------------------------
extern "C" void kernel_launch(void* const* d_in, const int* in_sizes, int n_in,
                              void* d_out, int out_size) {
    const float* entity  = (const float*)d_in[0];
    const float* attr1h  = (const float*)d_in[1];
    const float* W_emb   = (const float*)d_in[2];
    const float* b_emb   = (const float*)d_in[3];
    const int*   h1      = (const int*)  d_in[4];
    const float* s1      = (const float*)d_in[5];
    const int*   h2      = (const int*)  d_in[6];
    const float* s2      = (const float*)d_in[7];
    const float* conv1_w = (const float*)d_in[8];
    const float* conv2_w = (const float*)d_in[9];

    float* out_map  = (float*)d_out;
    float* out_feat = (float*)d_out + (size_t)BD * HWD;

    const int k3_smem = (CD * TILE + CD * O1 + 2048 + 8 * 65 + TILE) * (int)sizeof(float);
    cudaFuncSetAttribute(k3_fused, cudaFuncAttributeMaxDynamicSharedMemorySize, k3_smem);

    k1_emb<<<dim3(BD, 8), 256>>>(attr1h, W_emb, b_emb, s1);
    k2_buildN<<<dim3(BD, 8), 128>>>(conv1_w, h1, h2, s2);
    k3_fused<<<dim3((HWD + TILE - 1) / TILE, BD), 128, k3_smem>>>(entity, conv2_w, out_map, out_feat);
}